// round 17
// baseline (speedup 1.0000x reference)
#include <cuda_runtime.h>
#include <cuda_fp16.h>
#include <cstdint>

#define N_NODES 90000
#define N_EDGES 540000
#define IN_F    30
#define N_GRAPH 10000
#define HIST_BLOCKS ((N_EDGES + 255) / 256)   // 2110
#define PREP_BLOCKS 128

// ======================= global scratch =======================
__device__ __half g_agg0_h[N_NODES * 32];
__device__ __half g_agg0_l[N_NODES * 32];
__device__ __half g_agg1s[N_NODES * 128];
__device__ __half g_agg1t[N_NODES * 128];
__device__ __half g_z1s[N_NODES * 128];
__device__ __half g_z1t[N_NODES * 128];
__device__ float g_z2s[N_NODES * 64];
__device__ float g_z2t[N_NODES * 64];
__device__ __half g_pwh[2][4][128 * 128];
__device__ __half g_pwl[2][4][128 * 128];
__device__ int g_deg[N_NODES];
__device__ int g_rowptr[N_NODES + 1];
__device__ int g_csrsrc[N_EDGES];
__device__ int g_bsum[128];
__device__ int g_boff[128];
__device__ int g_scan_ctr;

__device__ __forceinline__ int rowptr_at(int i) {
    return g_rowptr[i] + g_boff[i >> 10];
}

__device__ __forceinline__ void fp16_split(float v, __half& h, __half& l) {
    h = __float2half(v);
    l = __float2half(v - __half2float(h));
}

// fp16 tensor-core MMA, fp32 accumulate (family-portable, sm_80+)
__device__ __forceinline__ void mma16816(float* d, const uint32_t* a, const uint32_t* b) {
    asm volatile(
        "mma.sync.aligned.m16n8k16.row.col.f32.f16.f16.f32 "
        "{%0,%1,%2,%3}, {%4,%5,%6,%7}, {%8,%9}, {%0,%1,%2,%3};\n"
        : "+f"(d[0]), "+f"(d[1]), "+f"(d[2]), "+f"(d[3])
        : "r"(a[0]), "r"(a[1]), "r"(a[2]), "r"(a[3]), "r"(b[0]), "r"(b[1]));
}
#define LDSM4(r0, r1, r2, r3, addr) \
    asm volatile("ldmatrix.sync.aligned.m8n8.x4.shared.b16 {%0,%1,%2,%3}, [%4];" \
        : "=r"(r0), "=r"(r1), "=r"(r2), "=r"(r3) : "r"(addr))

__device__ __forceinline__ uint32_t smem_u32(const void* p) {
    uint32_t a;
    asm("{ .reg .u64 t; cvta.to.shared.u64 t, %1; cvt.u32.u64 %0, t; }" : "=r"(a) : "l"(p));
    return a;
}

// ======================= fused histogram + weight prep =======================
__global__ void hist_prep_kernel(const int* __restrict__ ei,
    const float* w0, const float* w1, const float* w2, const float* w3,
    const float* w4, const float* w5, const float* w6, const float* w7)
{
    int b = blockIdx.x;
    if (b < HIST_BLOCKS) {
        if (b == 0 && threadIdx.x == 0) g_scan_ctr = 0;
        int e = b * 256 + threadIdx.x;
        if (e < N_EDGES) atomicAdd(&g_deg[ei[N_EDGES + e]], 1);
        return;
    }
    const int KREAL[4] = { IN_F, 128, 128, 128 };
    const int KSM[4]   = { 32, 128, 128, 128 };
    const int NOUT[4]  = { 128, 128, 128, 64 };
    const int CUM[9]   = { 0, 4096, 20480, 36864, 45056,
                           49152, 65536, 81920, 90112 };
    const float* Ws[8] = { w0, w1, w2, w3, w4, w5, w6, w7 };
    const int TOTAL = 90112;
    int pb = b - HIST_BLOCKS;
    for (int idx = pb * 256 + threadIdx.x; idx < TOTAL; idx += PREP_BLOCKS * 256) {
        int y = 0;
        #pragma unroll
        for (int j = 1; j < 8; j++) if (idx >= CUM[j]) y = j;
        int li = y & 3, br = y >> 2;
        int il = idx - CUM[y];
        int n = il / KSM[li], k = il - n * KSM[li];
        float v = (k < KREAL[li]) ? Ws[y][k * NOUT[li] + n] : 0.f;
        __half h, l;
        fp16_split(v, h, l);
        g_pwh[br][li][il] = h;
        g_pwl[br][li][il] = l;
    }
}

// ======================= single-pass scan =======================
__global__ void scan_kernel() {
    __shared__ int wsum[32];
    __shared__ int sm2[128];
    __shared__ int isLast;
    int t = threadIdx.x, lane = t & 31, wrp = t >> 5;
    int idx = blockIdx.x * 1024 + t;
    int d = (idx < N_NODES) ? g_deg[idx] : 0;
    int v = d;
    #pragma unroll
    for (int off = 1; off < 32; off <<= 1) {
        int u = __shfl_up_sync(0xffffffffu, v, off);
        if (lane >= off) v += u;
    }
    if (lane == 31) wsum[wrp] = v;
    __syncthreads();
    if (wrp == 0) {
        int s = wsum[lane];
        #pragma unroll
        for (int off = 1; off < 32; off <<= 1) {
            int u = __shfl_up_sync(0xffffffffu, s, off);
            if (lane >= off) s += u;
        }
        wsum[lane] = s;
    }
    __syncthreads();
    int incl = ((wrp > 0) ? wsum[wrp - 1] : 0) + v;
    if (idx < N_NODES) g_rowptr[idx] = incl - d;
    if (t == 1023) g_bsum[blockIdx.x] = incl;
    __threadfence();
    if (t == 0) {
        int done = atomicAdd(&g_scan_ctr, 1);
        isLast = (done == (int)gridDim.x - 1);
    }
    __syncthreads();
    if (!isLast) return;
    int nb = gridDim.x;
    int bv = (t < nb) ? ((volatile int*)g_bsum)[t] : 0;
    if (t < 128) sm2[t] = bv;
    __syncthreads();
    #pragma unroll
    for (int off = 1; off < 128; off <<= 1) {
        int u = (t >= off && t < 128) ? sm2[t - off] : 0;
        __syncthreads();
        if (t < 128) sm2[t] += u;
        __syncthreads();
    }
    if (t < nb) g_boff[t] = sm2[t] - bv;
    if (t == (N_NODES >> 10)) g_rowptr[N_NODES] = N_EDGES - (sm2[t] - bv);
}

// fill: position via atomicSub on deg (deg drained to 0)
__global__ void fill_kernel(const int* __restrict__ ei) {
    int e = blockIdx.x * blockDim.x + threadIdx.x;
    if (e < N_EDGES) {
        int src = ei[e];
        int dst = ei[N_EDGES + e];
        int pos = rowptr_at(dst) + atomicSub(&g_deg[dst], 1) - 1;
        g_csrsrc[pos] = src;
    }
}

// ======================= layer-1 aggregation: 2 edge-groups x float2 lanes =======================
// warp per node. half = lane>>4 handles edges e+2i+half; sub = lane&15 covers cols sub*2..+1 (sub<15).
__global__ void agg0_kernel(const float* __restrict__ x) {
    int w = (blockIdx.x * blockDim.x + threadIdx.x) >> 5;
    int lane = threadIdx.x & 31;
    if (w >= N_NODES) return;
    int half = lane >> 4, sub = lane & 15;
    bool act = (sub < 15);
    float2 acc = make_float2(0.f, 0.f);
    if (half == 0 && act) acc = *(const float2*)(x + (size_t)w * IN_F + sub * 2);
    int s0 = rowptr_at(w), s1 = rowptr_at(w + 1);
    for (int e = s0; e < s1; e += 16) {
        int idx[8];
        #pragma unroll
        for (int j = 0; j < 8; j++) {
            int ee = e + 2 * j + half;
            idx[j] = (ee < s1) ? g_csrsrc[ee] : -1;
        }
        float2 v[8];
        #pragma unroll
        for (int j = 0; j < 8; j++)
            v[j] = (idx[j] >= 0 && act) ? *(const float2*)(x + (size_t)idx[j] * IN_F + sub * 2)
                                        : make_float2(0.f, 0.f);
        #pragma unroll
        for (int j = 0; j < 8; j++) { acc.x += v[j].x; acc.y += v[j].y; }
    }
    acc.x += __shfl_xor_sync(0xffffffffu, acc.x, 16);
    acc.y += __shfl_xor_sync(0xffffffffu, acc.y, 16);
    if (half == 0) {
        if (act) {
            __half h0, l0, h1, l1;
            fp16_split(acc.x, h0, l0);
            fp16_split(acc.y, h1, l1);
            __half2 ph; ph.x = h0; ph.y = h1;
            __half2 pl; pl.x = l0; pl.y = l1;
            *(uint32_t*)(g_agg0_h + w * 32 + sub * 2) = *(uint32_t*)&ph;
            *(uint32_t*)(g_agg0_l + w * 32 + sub * 2) = *(uint32_t*)&pl;
        } else {
            *(uint32_t*)(g_agg0_h + w * 32 + 30) = 0u;   // pad cols 30,31
            *(uint32_t*)(g_agg0_l + w * 32 + 30) = 0u;
        }
    }
}

// ======================= layer-2 aggregation: 2 edge-groups x uint4 lanes =======================
// warp per (node, branch). half = lane>>4 handles edges e+2i+half; sub = lane&15 covers 8 halfs.
__global__ void agg1_kernel() {
    int br = blockIdx.y;
    const uint4* Z = (const uint4*)(br ? g_z1t : g_z1s);   // 16 uint4 per 128-half row
    int w = (blockIdx.x * blockDim.x + threadIdx.x) >> 5;
    int lane = threadIdx.x & 31;
    if (w >= N_NODES) return;
    int half = lane >> 4, sub = lane & 15;
    float acc[8] = {};
    if (half == 0) {
        uint4 sv = Z[(size_t)w * 16 + sub];
        float2 a = __half22float2(*(__half2*)&sv.x);
        float2 b = __half22float2(*(__half2*)&sv.y);
        float2 c = __half22float2(*(__half2*)&sv.z);
        float2 d = __half22float2(*(__half2*)&sv.w);
        acc[0] = a.x; acc[1] = a.y; acc[2] = b.x; acc[3] = b.y;
        acc[4] = c.x; acc[5] = c.y; acc[6] = d.x; acc[7] = d.y;
    }
    int s0 = rowptr_at(w), s1 = rowptr_at(w + 1);
    for (int e = s0; e < s1; e += 16) {
        int idx[8];
        #pragma unroll
        for (int j = 0; j < 8; j++) {
            int ee = e + 2 * j + half;
            idx[j] = (ee < s1) ? g_csrsrc[ee] : -1;
        }
        uint4 v[8];
        #pragma unroll
        for (int j = 0; j < 8; j++)
            v[j] = (idx[j] >= 0) ? Z[(size_t)idx[j] * 16 + sub]
                                 : make_uint4(0u, 0u, 0u, 0u);
        #pragma unroll
        for (int j = 0; j < 8; j++) {
            float2 a = __half22float2(*(__half2*)&v[j].x);
            float2 b = __half22float2(*(__half2*)&v[j].y);
            float2 c = __half22float2(*(__half2*)&v[j].z);
            float2 d = __half22float2(*(__half2*)&v[j].w);
            acc[0] += a.x; acc[1] += a.y; acc[2] += b.x; acc[3] += b.y;
            acc[4] += c.x; acc[5] += c.y; acc[6] += d.x; acc[7] += d.y;
        }
    }
    #pragma unroll
    for (int c = 0; c < 8; c++)
        acc[c] += __shfl_xor_sync(0xffffffffu, acc[c], 16);
    if (half == 0) {
        __half2 p0 = __floats2half2_rn(acc[0], acc[1]);
        __half2 p1 = __floats2half2_rn(acc[2], acc[3]);
        __half2 p2 = __floats2half2_rn(acc[4], acc[5]);
        __half2 p3 = __floats2half2_rn(acc[6], acc[7]);
        uint4 o;
        o.x = *(uint32_t*)&p0; o.y = *(uint32_t*)&p1;
        o.z = *(uint32_t*)&p2; o.w = *(uint32_t*)&p3;
        uint4* dst = (uint4*)(br ? g_agg1t : g_agg1s);
        dst[(size_t)w * 16 + sub] = o;
    }
}

// ======================= W chunk loader: 64-col chunk, XOR-swizzled, pitch 64 halfs
__device__ __forceinline__ void load_w_chunk(
    __half* WH, __half* WL,
    const __half* __restrict__ Wh, const __half* __restrict__ Wl,
    int rows, int KS, int kk, int tid)
{
    for (int i = tid; i < rows * 8; i += 256) {
        int r = i >> 3, g = i & 7;
        int col = kk * 64 + g * 8;
        float4 vh = make_float4(0.f, 0.f, 0.f, 0.f), vl = vh;
        if (col < KS) {
            vh = *(const float4*)(Wh + r * KS + col);
            vl = *(const float4*)(Wl + r * KS + col);
        }
        int dst = r * 64 + ((g ^ (r & 7)) << 3);
        *(float4*)(WH + dst) = vh;
        *(float4*)(WL + dst) = vl;
    }
}

// ======================= fused 2-layer MLP, M-tile 64, 3 CTA/SM (frozen) =======================
template<int K1, int NT2, int ASPLIT>
__global__ __launch_bounds__(256, 3) void mlp_kernel(
    const float* __restrict__ B1a, const float* __restrict__ B1b,
    const float* __restrict__ B2a, const float* __restrict__ B2b)
{
    constexpr int NOUT2 = NT2 * 32;
    constexpr int GA = K1 / 8;
    constexpr int KCH1 = (K1 + 63) / 64;
    constexpr int KS1 = K1 / 16;
    extern __shared__ char smraw[];
    __half* AS = (__half*)smraw;
    __half* WH = AS + 64 * 128;
    __half* WL = WH + 128 * 64;

    int tid = threadIdx.x, lane = tid & 31, wid = tid >> 5;
    int warpM = wid & 1, warpN = wid >> 1;
    int by = blockIdx.y;
    int row0 = blockIdx.x * 64;
    int lg = lane >> 2, lt = lane & 3;

    int l1 = (K1 == 32) ? 0 : 2;
    const __half* Ag  = (K1 == 32) ? g_agg0_h : (by ? g_agg1t : g_agg1s);
    const __half* Agl = g_agg0_l;
    const __half* W1h = g_pwh[by][l1];
    const __half* W1l = g_pwl[by][l1];
    const __half* W2h = g_pwh[by][l1 + 1];
    const __half* W2l = g_pwl[by][l1 + 1];
    const float* B1 = by ? B1b : B1a;
    const float* B2 = by ? B2b : B2a;

    for (int i = tid; i < 64 * GA; i += 256) {
        int r = i / GA, g = i % GA;
        int col = g * 8;
        int gr = row0 + r;
        float4 v = make_float4(0.f, 0.f, 0.f, 0.f);
        if (gr < N_NODES) v = *(const float4*)(Ag + (size_t)gr * K1 + col);
        int dst = r * 128 + ((g ^ (r & 7)) << 3);
        *(float4*)(AS + dst) = v;
        if (ASPLIT) {
            float4 vl = make_float4(0.f, 0.f, 0.f, 0.f);
            if (gr < N_NODES) vl = *(const float4*)(Agl + (size_t)gr * K1 + col);
            *(float4*)(AS + dst + 64) = vl;
        }
    }
    load_w_chunk(WH, WL, W1h, W1l, 128, K1, 0, tid);
    __syncthreads();

    int a_row = lane & 15;
    int xA = lane & 7;
    int g0A = lane >> 4;
    int b_row = (lane & 7) + ((lane >> 4) & 1) * 8;
    int xW = b_row & 7;
    int g0W = (lane >> 3) & 1;

    uint32_t uAS = smem_u32(AS);
    uint32_t uWH = smem_u32(WH), uWL = smem_u32(WL);

    uint32_t aRB[2];
    #pragma unroll
    for (int tm = 0; tm < 2; tm++) {
        int R = warpM * 32 + tm * 16;
        aRB[tm] = uAS + (R + a_row) * 256;
    }

    float acc[2][4][4];
    #pragma unroll
    for (int tm = 0; tm < 2; tm++)
        #pragma unroll
        for (int tn = 0; tn < 4; tn++)
            #pragma unroll
            for (int q = 0; q < 4; q++) acc[tm][tn][q] = 0.f;

    {
        uint32_t wRB_H[2], wRB_L[2];
        #pragma unroll
        for (int pp = 0; pp < 2; pp++) {
            int N0 = warpN * 32 + pp * 16;
            wRB_H[pp] = uWH + (N0 + b_row) * 128;
            wRB_L[pp] = uWL + (N0 + b_row) * 128;
        }
        constexpr int NKS = (KCH1 == 1) ? KS1 : 4;
        #pragma unroll
        for (int kk = 0; kk < KCH1; kk++) {
            if (kk > 0) {
                __syncthreads();
                load_w_chunk(WH, WL, W1h, W1l, 128, K1, kk, tid);
                __syncthreads();
            }
            #pragma unroll
            for (int ks = 0; ks < NKS; ks++) {
                int gs = kk * 4 + ks;
                uint32_t ao = (uint32_t)(((gs * 2 + g0A) ^ xA) << 4);
                uint32_t wo = (uint32_t)(((ks * 2 + g0W) ^ xW) << 4);
                uint32_t a[2][4], al[2][4];
                #pragma unroll
                for (int tm = 0; tm < 2; tm++) {
                    LDSM4(a[tm][0], a[tm][1], a[tm][2], a[tm][3], aRB[tm] + ao);
                    if (ASPLIT)
                        LDSM4(al[tm][0], al[tm][1], al[tm][2], al[tm][3], aRB[tm] + ao + 128);
                }
                #pragma unroll
                for (int pp = 0; pp < 2; pp++) {
                    uint32_t bh[4], bl[4];
                    LDSM4(bh[0], bh[1], bh[2], bh[3], wRB_H[pp] + wo);
                    LDSM4(bl[0], bl[1], bl[2], bl[3], wRB_L[pp] + wo);
                    #pragma unroll
                    for (int hf = 0; hf < 2; hf++) {
                        int tn = pp * 2 + hf;
                        #pragma unroll
                        for (int tm = 0; tm < 2; tm++) {
                            mma16816(acc[tm][tn], a[tm], bh + 2 * hf);
                            mma16816(acc[tm][tn], a[tm], bl + 2 * hf);
                            if (ASPLIT)
                                mma16816(acc[tm][tn], al[tm], bh + 2 * hf);
                        }
                    }
                }
            }
        }
    }
    __syncthreads();

    #pragma unroll
    for (int tm = 0; tm < 2; tm++) {
        int m = warpM * 32 + tm * 16 + lg;
        #pragma unroll
        for (int tn = 0; tn < 4; tn++) {
            int n = warpN * 32 + tn * 8 + lt * 2;
            float2 bv = *(const float2*)(B1 + n);
            float v0 = fmaxf(acc[tm][tn][0] + bv.x, 0.f);
            float v1 = fmaxf(acc[tm][tn][1] + bv.y, 0.f);
            float v2 = fmaxf(acc[tm][tn][2] + bv.x, 0.f);
            float v3 = fmaxf(acc[tm][tn][3] + bv.y, 0.f);
            int off0 = m * 128 + (((n >> 3) ^ (m & 7)) << 3) + (n & 7);
            __half2 p0 = __floats2half2_rn(v0, v1);
            *(uint32_t*)(AS + off0) = *(uint32_t*)&p0;
            int off1 = (m + 8) * 128 + (((n >> 3) ^ (m & 7)) << 3) + (n & 7);
            __half2 p1 = __floats2half2_rn(v2, v3);
            *(uint32_t*)(AS + off1) = *(uint32_t*)&p1;
        }
    }
    load_w_chunk(WH, WL, W2h, W2l, NOUT2, 128, 0, tid);
    __syncthreads();

    float acc2[2][NT2][4];
    #pragma unroll
    for (int tm = 0; tm < 2; tm++)
        #pragma unroll
        for (int tn = 0; tn < NT2; tn++)
            #pragma unroll
            for (int q = 0; q < 4; q++) acc2[tm][tn][q] = 0.f;

    {
        uint32_t wRB_H[NT2 / 2], wRB_L[NT2 / 2];
        #pragma unroll
        for (int pp = 0; pp < NT2 / 2; pp++) {
            int N0 = warpN * (NOUT2 / 4) + pp * 16;
            wRB_H[pp] = uWH + (N0 + b_row) * 128;
            wRB_L[pp] = uWL + (N0 + b_row) * 128;
        }
        #pragma unroll
        for (int kk = 0; kk < 2; kk++) {
            if (kk > 0) {
                __syncthreads();
                load_w_chunk(WH, WL, W2h, W2l, NOUT2, 128, 1, tid);
                __syncthreads();
            }
            #pragma unroll
            for (int ks = 0; ks < 4; ks++) {
                int gs = kk * 4 + ks;
                uint32_t ao = (uint32_t)(((gs * 2 + g0A) ^ xA) << 4);
                uint32_t wo = (uint32_t)(((ks * 2 + g0W) ^ xW) << 4);
                uint32_t a[2][4];
                #pragma unroll
                for (int tm = 0; tm < 2; tm++)
                    LDSM4(a[tm][0], a[tm][1], a[tm][2], a[tm][3], aRB[tm] + ao);
                #pragma unroll
                for (int pp = 0; pp < NT2 / 2; pp++) {
                    uint32_t bh[4], bl[4];
                    LDSM4(bh[0], bh[1], bh[2], bh[3], wRB_H[pp] + wo);
                    LDSM4(bl[0], bl[1], bl[2], bl[3], wRB_L[pp] + wo);
                    #pragma unroll
                    for (int hf = 0; hf < 2; hf++) {
                        int tn = pp * 2 + hf;
                        #pragma unroll
                        for (int tm = 0; tm < 2; tm++) {
                            mma16816(acc2[tm][tn], a[tm], bh + 2 * hf);
                            mma16816(acc2[tm][tn], a[tm], bl + 2 * hf);
                        }
                    }
                }
            }
        }
    }

    #pragma unroll
    for (int tm = 0; tm < 2; tm++) {
        int m = warpM * 32 + tm * 16 + lg;
        #pragma unroll
        for (int tn = 0; tn < NT2; tn++) {
            int n = warpN * (NOUT2 / 4) + tn * 8 + lt * 2;
            float2 bv = *(const float2*)(B2 + n);
            float o0x = acc2[tm][tn][0] + bv.x, o0y = acc2[tm][tn][1] + bv.y;
            float o1x = acc2[tm][tn][2] + bv.x, o1y = acc2[tm][tn][3] + bv.y;
            int g0 = row0 + m, g1 = row0 + m + 8;
            if (K1 == 32) {
                __half* z1 = by ? g_z1t : g_z1s;
                if (g0 < N_NODES) {
                    __half2 p = __floats2half2_rn(o0x, o0y);
                    *(uint32_t*)(z1 + (size_t)g0 * NOUT2 + n) = *(uint32_t*)&p;
                }
                if (g1 < N_NODES) {
                    __half2 p = __floats2half2_rn(o1x, o1y);
                    *(uint32_t*)(z1 + (size_t)g1 * NOUT2 + n) = *(uint32_t*)&p;
                }
            } else {
                float* z2 = by ? g_z2t : g_z2s;
                if (g0 < N_NODES) {
                    float2 o; o.x = o0x; o.y = o0y;
                    *(float2*)(z2 + (size_t)g0 * NOUT2 + n) = o;
                }
                if (g1 < N_NODES) {
                    float2 o; o.x = o1x; o.y = o1y;
                    *(float2*)(z2 + (size_t)g1 * NOUT2 + n) = o;
                }
            }
        }
    }
}

// ======================= per-graph 9x9 gram: 4 graphs per block =======================
__global__ void final_kernel(float* __restrict__ out) {
    __shared__ float zs[4][9 * 64];
    __shared__ float zt[4][9 * 64];
    int g0 = blockIdx.x * 4;
    int tid = threadIdx.x;
    const float4* ps = (const float4*)(g_z2s + (size_t)g0 * 9 * 64);
    const float4* pt = (const float4*)(g_z2t + (size_t)g0 * 9 * 64);
    for (int i = tid; i < 576; i += 512) {
        ((float4*)zs)[i] = ps[i];
        ((float4*)zt)[i] = pt[i];
    }
    __syncthreads();
    int gg = tid >> 7, t = tid & 127;
    if (t < 81) {
        int i = t / 9, j = t % 9;
        float acc = 0.f;
        #pragma unroll
        for (int k = 0; k < 64; k++) acc += zs[gg][i * 64 + k] * zt[gg][j * 64 + k];
        out[((g0 + gg) * 9 + i) * 9 + j] = acc;
    }
}

// ======================= launch =======================
extern "C" void kernel_launch(void* const* d_in, const int* in_sizes, int n_in,
                              void* d_out, int out_size) {
    const float* x  = (const float*)d_in[0];
    const int*   ei = (const int*)d_in[1];
    const float* B[2][4] = {
        { (const float*)d_in[3],  (const float*)d_in[5],  (const float*)d_in[7],  (const float*)d_in[9]  },
        { (const float*)d_in[11], (const float*)d_in[13], (const float*)d_in[15], (const float*)d_in[17] }
    };
    float* out = (float*)d_out;

    const int SMEM = (64 * 128 + 2 * 128 * 64) * 2;   // 49152 B -> 3 CTA/SM
    cudaFuncSetAttribute(mlp_kernel<32, 4, 1>,  cudaFuncAttributeMaxDynamicSharedMemorySize, SMEM);
    cudaFuncSetAttribute(mlp_kernel<128, 2, 0>, cudaFuncAttributeMaxDynamicSharedMemorySize, SMEM);

    const int GEMM_BLOCKS = (N_NODES + 63) / 64;
    const int WARP_BLOCKS = (N_NODES * 32 + 255) / 256;
    const int SCAN_BLOCKS = (N_NODES + 1023) / 1024;

    void* p_deg = nullptr;
    cudaGetSymbolAddress(&p_deg, g_deg);
    cudaMemsetAsync(p_deg, 0, N_NODES * sizeof(int));

    hist_prep_kernel<<<HIST_BLOCKS + PREP_BLOCKS, 256>>>(ei,
        (const float*)d_in[2],  (const float*)d_in[4],  (const float*)d_in[6],  (const float*)d_in[8],
        (const float*)d_in[10], (const float*)d_in[12], (const float*)d_in[14], (const float*)d_in[16]);

    scan_kernel<<<SCAN_BLOCKS, 1024>>>();
    fill_kernel<<<(N_EDGES + 255) / 256, 256>>>(ei);

    agg0_kernel<<<WARP_BLOCKS, 256>>>(x);

    mlp_kernel<32, 4, 1><<<dim3(GEMM_BLOCKS, 2), 256, SMEM>>>(B[0][0], B[1][0], B[0][1], B[1][1]);

    agg1_kernel<<<dim3(WARP_BLOCKS, 2), 256>>>();

    mlp_kernel<128, 2, 0><<<dim3(GEMM_BLOCKS, 2), 256, SMEM>>>(B[0][2], B[1][2], B[0][3], B[1][3]);

    final_kernel<<<(N_GRAPH + 3) / 4, 512>>>(out);
}